// round 2
// baseline (speedup 1.0000x reference)
#include <cuda_runtime.h>
#include <cuda_bf16.h>
#include <cstdint>

#define N_NODES 10000
#define EDGES   160000
#define ETOT    (EDGES + N_NODES)
#define EMBED   128
#define HEADS   16
#define HC      (HEADS * EMBED)   // 2048
#define NEG_SLOPE 0.2f
#define M_SENT  (-1e30f)

// ---------------- scratch (device globals; no allocation allowed) -------------
__device__ int   g_is64;
__device__ int   g_src[EDGES];
__device__ int   g_dst[EDGES];
__device__ int   g_deg[N_NODES];
__device__ int   g_rowptr[N_NODES + 1];
__device__ int   g_cursor[N_NODES];
__device__ int   g_col[ETOT];

__device__ float g_h1[(size_t)N_NODES * HC];     // 81.9 MB
__device__ float g_als1[N_NODES * HEADS];
__device__ float g_ald1[N_NODES * HEADS];
__device__ float g_x2[(size_t)N_NODES * HC];     // 81.9 MB
__device__ float g_h2[(size_t)N_NODES * EMBED];
__device__ float g_als2[N_NODES];
__device__ float g_ald2[N_NODES];
__device__ float g_out2[(size_t)N_NODES * EMBED];

// ---------------- edge decode ------------------------------------------------
__global__ void detect_kernel(const void* __restrict__ ei) {
    if (threadIdx.x == 0 && blockIdx.x == 0) {
        const long long* p = (const long long*)ei;
        int ok64 = 1;
        for (int i = 0; i < 256; i++) {
            long long v = p[i];
            if (v < 0 || v >= N_NODES) { ok64 = 0; break; }
        }
        g_is64 = ok64;
    }
}

__global__ void decode_kernel(const void* __restrict__ ei, int E) {
    int i = blockIdx.x * blockDim.x + threadIdx.x;
    if (i >= 2 * E) return;
    int is64 = g_is64;
    long long v = is64 ? ((const long long*)ei)[i] : (long long)((const int*)ei)[i];
    int vi = (int)v;
    if (i < E) g_src[i] = vi;
    else       g_dst[i - E] = vi;
}

// ---------------- CSR build --------------------------------------------------
__global__ void initdeg_kernel(int n) {
    int i = blockIdx.x * blockDim.x + threadIdx.x;
    if (i < n) g_deg[i] = 1;   // self loop
}

__global__ void count_kernel(int E) {
    int i = blockIdx.x * blockDim.x + threadIdx.x;
    if (i < E) atomicAdd(&g_deg[g_dst[i]], 1);
}

__global__ void scan_kernel(int n) {
    __shared__ int wsum[32];
    int tid = threadIdx.x;
    int CH = (n + 1023) / 1024;
    int base = tid * CH;
    int s = 0;
    for (int k = 0; k < CH; k++) {
        int idx = base + k;
        if (idx < n) s += g_deg[idx];
    }
    int lane = tid & 31, wid = tid >> 5;
    int v = s;
    #pragma unroll
    for (int o = 1; o < 32; o <<= 1) {
        int t = __shfl_up_sync(0xffffffffu, v, o);
        if (lane >= o) v += t;
    }
    if (lane == 31) wsum[wid] = v;
    __syncthreads();
    if (wid == 0) {
        int w = wsum[lane];
        #pragma unroll
        for (int o = 1; o < 32; o <<= 1) {
            int t = __shfl_up_sync(0xffffffffu, w, o);
            if (lane >= o) w += t;
        }
        wsum[lane] = w;
    }
    __syncthreads();
    int excl = v - s + (wid ? wsum[wid - 1] : 0);
    int running = excl;
    for (int k = 0; k < CH; k++) {
        int idx = base + k;
        if (idx < n) {
            g_rowptr[idx] = running;
            g_cursor[idx] = running;
            running += g_deg[idx];
        }
    }
    if (tid == 0) g_rowptr[n] = wsum[31];
}

__global__ void fill_edges_kernel(int E) {
    int i = blockIdx.x * blockDim.x + threadIdx.x;
    if (i < E) {
        int d = g_dst[i];
        int pos = atomicAdd(&g_cursor[d], 1);
        g_col[pos] = g_src[i];
    }
}

__global__ void fill_self_kernel(int n) {
    int i = blockIdx.x * blockDim.x + threadIdx.x;
    if (i < n) {
        int pos = atomicAdd(&g_cursor[i], 1);
        g_col[pos] = i;
    }
}

// ---------------- fp32 GEMM (BM=128, BN=64, BK=32, 8x4 per thread) ----------
template <int BM, int BN, int BK>
__device__ __forceinline__ void gemm_dev(const float* __restrict__ A,
                                         const float* __restrict__ B,
                                         float* __restrict__ C,
                                         int M, int N, int K) {
    __shared__ float As[BK][BM + 4];
    __shared__ float Bs[BK][BN];
    const int tid = threadIdx.x;
    const int bm0 = blockIdx.y * BM;
    const int bn0 = blockIdx.x * BN;
    const int tm = tid >> 4, tn = tid & 15;
    const int r0 = tm * 8, cb = tn * 4;

    float acc[8][4];
    #pragma unroll
    for (int i = 0; i < 8; i++)
        #pragma unroll
        for (int j = 0; j < 4; j++) acc[i][j] = 0.f;

    for (int kt = 0; kt < K; kt += BK) {
        // load A tile (transposed into As[k][m])
        #pragma unroll
        for (int i = 0; i < (BM * BK) / (256 * 4); i++) {
            int idx = tid + i * 256;
            int row = idx / (BK / 4);
            int k4 = idx % (BK / 4);
            float4 v = make_float4(0.f, 0.f, 0.f, 0.f);
            int gm = bm0 + row;
            if (gm < M)
                v = *(const float4*)(A + (size_t)gm * K + kt + k4 * 4);
            As[k4 * 4 + 0][row] = v.x;
            As[k4 * 4 + 1][row] = v.y;
            As[k4 * 4 + 2][row] = v.z;
            As[k4 * 4 + 3][row] = v.w;
        }
        // load B tile
        #pragma unroll
        for (int i = 0; i < (BK * BN) / (256 * 4); i++) {
            int idx = tid + i * 256;
            int row = idx / (BN / 4);
            int n4 = idx % (BN / 4);
            float4 v = *(const float4*)(B + (size_t)(kt + row) * N + bn0 + n4 * 4);
            *(float4*)&Bs[row][n4 * 4] = v;
        }
        __syncthreads();
        #pragma unroll
        for (int k = 0; k < BK; k++) {
            float4 b = *(float4*)&Bs[k][cb];
            float4 a0 = *(float4*)&As[k][r0];
            float4 a1 = *(float4*)&As[k][r0 + 4];
            float av[8] = {a0.x, a0.y, a0.z, a0.w, a1.x, a1.y, a1.z, a1.w};
            #pragma unroll
            for (int i = 0; i < 8; i++) {
                acc[i][0] += av[i] * b.x;
                acc[i][1] += av[i] * b.y;
                acc[i][2] += av[i] * b.z;
                acc[i][3] += av[i] * b.w;
            }
        }
        __syncthreads();
    }
    #pragma unroll
    for (int i = 0; i < 8; i++) {
        int gm = bm0 + r0 + i;
        if (gm < M) {
            float4 o = make_float4(acc[i][0], acc[i][1], acc[i][2], acc[i][3]);
            *(float4*)(C + (size_t)gm * N + bn0 + cb) = o;
        }
    }
}

__global__ __launch_bounds__(256) void gemm1_kernel(const float* __restrict__ x,
                                                    const float* __restrict__ W1,
                                                    int n) {
    gemm_dev<128, 64, 32>(x, W1, g_h1, n, HC, EMBED);
}

__global__ __launch_bounds__(256) void gemm2_kernel(const float* __restrict__ W2,
                                                    int n) {
    gemm_dev<128, 64, 32>(g_x2, W2, g_h2, n, EMBED, HC);
}

// ---------------- attention logits ------------------------------------------
__global__ void al1_kernel(const float* __restrict__ as1,
                           const float* __restrict__ ad1) {
    int nno = blockIdx.x;
    int wid = threadIdx.x >> 5, lane = threadIdx.x & 31;  // 512 threads, 16 warps
    int h = wid;
    float4 hv = *(const float4*)(g_h1 + (size_t)nno * HC + h * EMBED + lane * 4);
    float4 as = *(const float4*)(as1 + h * EMBED + lane * 4);
    float4 ad = *(const float4*)(ad1 + h * EMBED + lane * 4);
    float ss = hv.x * as.x + hv.y * as.y + hv.z * as.z + hv.w * as.w;
    float sd = hv.x * ad.x + hv.y * ad.y + hv.z * ad.z + hv.w * ad.w;
    #pragma unroll
    for (int o = 16; o > 0; o >>= 1) {
        ss += __shfl_down_sync(0xffffffffu, ss, o);
        sd += __shfl_down_sync(0xffffffffu, sd, o);
    }
    if (lane == 0) {
        g_als1[nno * HEADS + h] = ss;
        g_ald1[nno * HEADS + h] = sd;
    }
}

__global__ void al2_kernel(const float* __restrict__ as2,
                           const float* __restrict__ ad2, int n) {
    int idx = blockIdx.x * 8 + (threadIdx.x >> 5);
    if (idx >= n) return;
    int lane = threadIdx.x & 31;
    float4 hv = *(const float4*)(g_h2 + (size_t)idx * EMBED + lane * 4);
    float4 a = *(const float4*)(as2 + lane * 4);
    float4 d = *(const float4*)(ad2 + lane * 4);
    float ss = hv.x * a.x + hv.y * a.y + hv.z * a.z + hv.w * a.w;
    float sd = hv.x * d.x + hv.y * d.y + hv.z * d.z + hv.w * d.w;
    #pragma unroll
    for (int o = 16; o > 0; o >>= 1) {
        ss += __shfl_down_sync(0xffffffffu, ss, o);
        sd += __shfl_down_sync(0xffffffffu, sd, o);
    }
    if (lane == 0) {
        g_als2[idx] = ss;
        g_ald2[idx] = sd;
    }
}

// ---------------- layer-1 aggregation (online softmax + ELU fused) ----------
__global__ void agg1_kernel(const float* __restrict__ b1) {
    int nno = blockIdx.x;
    int t = threadIdx.x;          // 256 threads
    int h = t >> 4;               // head
    int c0 = (t & 15) * 8;        // channel base
    int beg = g_rowptr[nno], end = g_rowptr[nno + 1];
    float ad = g_ald1[nno * HEADS + h];
    float m = M_SENT, s = 0.f;
    float a[8];
    #pragma unroll
    for (int i = 0; i < 8; i++) a[i] = 0.f;

    for (int j = beg; j < end; j++) {
        int src = __ldg(&g_col[j]);
        float lg = __ldg(&g_als1[src * HEADS + h]) + ad;
        lg = lg > 0.f ? lg : NEG_SLOPE * lg;
        const float4* hp = (const float4*)(g_h1 + (size_t)src * HC + h * EMBED + c0);
        float4 h0 = __ldg(hp), h1v = __ldg(hp + 1);
        float hv[8] = {h0.x, h0.y, h0.z, h0.w, h1v.x, h1v.y, h1v.z, h1v.w};
        if (lg > m) {
            float sc = (m == M_SENT) ? 0.f : __expf(m - lg);
            s = s * sc + 1.f;
            #pragma unroll
            for (int i = 0; i < 8; i++) a[i] = a[i] * sc + hv[i];
            m = lg;
        } else {
            float p = __expf(lg - m);
            s += p;
            #pragma unroll
            for (int i = 0; i < 8; i++) a[i] += p * hv[i];
        }
    }
    float inv = 1.f / (s + 1e-16f);
    float o[8];
    #pragma unroll
    for (int i = 0; i < 8; i++) {
        float v = a[i] * inv + b1[h * EMBED + c0 + i];
        o[i] = v > 0.f ? v : (__expf(v) - 1.f);   // ELU fused
    }
    float* dst = g_x2 + (size_t)nno * HC + h * EMBED + c0;
    *(float4*)dst = make_float4(o[0], o[1], o[2], o[3]);
    *(float4*)(dst + 4) = make_float4(o[4], o[5], o[6], o[7]);
}

// ---------------- layer-2 aggregation ----------------------------------------
__global__ void agg2_kernel(const float* __restrict__ b2) {
    int nno = blockIdx.x;
    int c = threadIdx.x;          // 128 threads
    int beg = g_rowptr[nno], end = g_rowptr[nno + 1];
    float ad = g_ald2[nno];
    float m = M_SENT, s = 0.f, acc = 0.f;
    for (int j = beg; j < end; j++) {
        int src = __ldg(&g_col[j]);
        float lg = __ldg(&g_als2[src]) + ad;
        lg = lg > 0.f ? lg : NEG_SLOPE * lg;
        float hv = __ldg(&g_h2[(size_t)src * EMBED + c]);
        if (lg > m) {
            float sc = (m == M_SENT) ? 0.f : __expf(m - lg);
            s = s * sc + 1.f;
            acc = acc * sc + hv;
            m = lg;
        } else {
            float p = __expf(lg - m);
            s += p;
            acc += p * hv;
        }
    }
    g_out2[(size_t)nno * EMBED + c] = acc / (s + 1e-16f) + b2[c];
}

// ---------------- classifier --------------------------------------------------
__global__ void cls_kernel(const float* __restrict__ Wc,
                           const float* __restrict__ bc,
                           float* __restrict__ out, int n) {
    int idx = blockIdx.x * 8 + (threadIdx.x >> 5);
    if (idx >= n) return;
    int lane = threadIdx.x & 31;
    float4 ov = *(const float4*)(g_out2 + (size_t)idx * EMBED + lane * 4);
    float4 w = *(const float4*)(Wc + lane * 4);
    float s = ov.x * w.x + ov.y * w.y + ov.z * w.z + ov.w * w.w;
    #pragma unroll
    for (int o = 16; o > 0; o >>= 1) s += __shfl_down_sync(0xffffffffu, s, o);
    if (lane == 0) out[idx] = s + bc[0];
}

// ---------------- launch ------------------------------------------------------
extern "C" void kernel_launch(void* const* d_in, const int* in_sizes, int n_in,
                              void* d_out, int out_size) {
    const float* x   = (const float*)d_in[0];
    const void*  ei  = d_in[1];
    const float* W1  = (const float*)d_in[2];
    const float* as1 = (const float*)d_in[3];
    const float* ad1 = (const float*)d_in[4];
    const float* b1  = (const float*)d_in[5];
    const float* W2  = (const float*)d_in[6];
    const float* as2 = (const float*)d_in[7];
    const float* ad2 = (const float*)d_in[8];
    const float* b2  = (const float*)d_in[9];
    const float* Wc  = (const float*)d_in[10];
    const float* bc  = (const float*)d_in[11];
    float* out = (float*)d_out;

    int E = in_sizes[1] / 2;       // element count is 2*E for either int dtype
    int n = in_sizes[0] / EMBED;   // 10000

    detect_kernel<<<1, 32>>>(ei);
    decode_kernel<<<(2 * E + 255) / 256, 256>>>(ei, E);
    initdeg_kernel<<<(n + 255) / 256, 256>>>(n);
    count_kernel<<<(E + 255) / 256, 256>>>(E);
    scan_kernel<<<1, 1024>>>(n);
    fill_edges_kernel<<<(E + 255) / 256, 256>>>(E);
    fill_self_kernel<<<(n + 255) / 256, 256>>>(n);

    dim3 g1(HC / 64, (n + 127) / 128);
    gemm1_kernel<<<g1, 256>>>(x, W1, n);
    al1_kernel<<<n, 512>>>(as1, ad1);
    agg1_kernel<<<n, 256>>>(b1);

    dim3 g2(EMBED / 64, (n + 127) / 128);
    gemm2_kernel<<<g2, 256>>>(W2, n);
    al2_kernel<<<(n + 7) / 8, 256>>>(as2, ad2, n);
    agg2_kernel<<<n, 128>>>(b2);
    cls_kernel<<<(n + 7) / 8, 256>>>(Wc, bc, out, n);
}

// round 4
// speedup vs baseline: 1.2249x; 1.2249x over previous
#include <cuda_runtime.h>
#include <cuda_bf16.h>
#include <cstdint>

#define N_NODES 10000
#define EDGES   160000
#define EMBED   128
#define HEADS   16
#define HC      2048
#define NEG_SLOPE 0.2f
#define M_SENT  (-1e30f)
#define MT      128
#define MTILES  79
#define MPAD    (MTILES * MT)      // 10112

// ===================== device scratch =======================================
__device__ int   g_is64;
__device__ int   g_src[EDGES];
__device__ int   g_dst[EDGES];
__device__ int   g_deg[N_NODES];
__device__ int   g_rowptr[N_NODES + 1];
__device__ int   g_cursor[N_NODES];
__device__ int   g_col[EDGES + N_NODES];

__device__ __nv_bfloat16 g_xhi[(size_t)MPAD * EMBED];
__device__ __nv_bfloat16 g_xlo[(size_t)MPAD * EMBED];
__device__ __nv_bfloat16 g_w1t_hi[(size_t)HC * EMBED];   // [n=2048][k=128]
__device__ __nv_bfloat16 g_w1t_lo[(size_t)HC * EMBED];
__device__ __nv_bfloat16 g_w2t_hi[(size_t)EMBED * HC];   // [n=128][k=2048]
__device__ __nv_bfloat16 g_w2t_lo[(size_t)EMBED * HC];
__device__ float g_h1[(size_t)MPAD * HC];                // 82.8 MB
__device__ float g_als1[MPAD * HEADS];
__device__ float g_ald1[MPAD * HEADS];
__device__ __nv_bfloat16 g_x2hi[(size_t)MPAD * HC];
__device__ __nv_bfloat16 g_x2lo[(size_t)MPAD * HC];
__device__ float g_h2[(size_t)MPAD * EMBED];
__device__ float g_als2[MPAD];
__device__ float g_ald2[MPAD];

// ===================== prep =================================================
template <int R, int C>
__device__ void transpose_cv(const float* __restrict__ src,
                             __nv_bfloat16* __restrict__ dhi,
                             __nv_bfloat16* __restrict__ dlo, int bx, int by) {
    __shared__ float tile[32][33];
    int tx = threadIdx.x & 31, ty0 = threadIdx.x >> 5;
    #pragma unroll
    for (int j = 0; j < 4; j++) {
        int r = by * 32 + ty0 + j * 8, c = bx * 32 + tx;
        tile[ty0 + j * 8][tx] = src[(size_t)r * C + c];
    }
    __syncthreads();
    #pragma unroll
    for (int j = 0; j < 4; j++) {
        int rd = bx * 32 + ty0 + j * 8;
        int cd = by * 32 + tx;
        float v = tile[tx][ty0 + j * 8];
        __nv_bfloat16 h = __float2bfloat16(v);
        dhi[(size_t)rd * R + cd] = h;
        dlo[(size_t)rd * R + cd] = __float2bfloat16(v - __bfloat162float(h));
    }
}

#define NB_X   5000
#define NB_W1  256
#define NB_W2  256
#define NB_DEG 40

__global__ void prep_kernel(const float* __restrict__ x,
                            const float* __restrict__ W1,
                            const float* __restrict__ W2,
                            const void* __restrict__ ei) {
    int b = blockIdx.x, t = threadIdx.x;
    if (b < NB_X) {
        int idx = b * 256 + t;
        if (idx < N_NODES * EMBED) {
            float v = x[idx];
            __nv_bfloat16 h = __float2bfloat16(v);
            g_xhi[idx] = h;
            g_xlo[idx] = __float2bfloat16(v - __bfloat162float(h));
        }
        return;
    }
    b -= NB_X;
    if (b < NB_W1) { transpose_cv<128, 2048>(W1, g_w1t_hi, g_w1t_lo, b & 63, b >> 6); return; }
    b -= NB_W1;
    if (b < NB_W2) { transpose_cv<2048, 128>(W2, g_w2t_hi, g_w2t_lo, b & 3, b >> 2); return; }
    b -= NB_W2;
    if (b < NB_DEG) {
        int idx = b * 256 + t;
        if (idx < N_NODES) g_deg[idx] = 1;
        return;
    }
    const long long* p = (const long long*)ei;
    long long v = p[t];
    int ok = (v >= 0 && v < N_NODES);
    int all = __syncthreads_and(ok);
    if (t == 0) g_is64 = all;
}

__global__ void decode_count_kernel(const void* __restrict__ ei, int E) {
    int i = blockIdx.x * blockDim.x + threadIdx.x;
    if (i >= 2 * E) return;
    int vi = g_is64 ? (int)((const long long*)ei)[i] : ((const int*)ei)[i];
    if (i < E) g_src[i] = vi;
    else { g_dst[i - E] = vi; atomicAdd(&g_deg[vi], 1); }
}

__global__ void scan_kernel(int n) {
    __shared__ int wsum[32];
    int tid = threadIdx.x;
    int CH = (n + 1023) / 1024;
    int base = tid * CH;
    int s = 0;
    for (int k = 0; k < CH; k++) { int idx = base + k; if (idx < n) s += g_deg[idx]; }
    int lane = tid & 31, wid = tid >> 5;
    int v = s;
    #pragma unroll
    for (int o = 1; o < 32; o <<= 1) {
        int t2 = __shfl_up_sync(0xffffffffu, v, o);
        if (lane >= o) v += t2;
    }
    if (lane == 31) wsum[wid] = v;
    __syncthreads();
    if (wid == 0) {
        int w = wsum[lane];
        #pragma unroll
        for (int o = 1; o < 32; o <<= 1) {
            int t2 = __shfl_up_sync(0xffffffffu, w, o);
            if (lane >= o) w += t2;
        }
        wsum[lane] = w;
    }
    __syncthreads();
    int excl = v - s + (wid ? wsum[wid - 1] : 0);
    int running = excl;
    for (int k = 0; k < CH; k++) {
        int idx = base + k;
        if (idx < n) {
            g_rowptr[idx] = running;
            g_cursor[idx] = running;
            running += g_deg[idx];
        }
    }
    if (tid == 0) g_rowptr[n] = wsum[31];
}

__global__ void fill_kernel(int E, int n) {
    int i = blockIdx.x * blockDim.x + threadIdx.x;
    if (i < E) {
        int d = g_dst[i];
        int pos = atomicAdd(&g_cursor[d], 1);
        g_col[pos] = g_src[i];
    } else if (i < E + n) {
        int v = i - E;
        int pos = atomicAdd(&g_cursor[v], 1);
        g_col[pos] = v;
    }
}

// ===================== mma.sync GEMM machinery ==============================
// warp grid 4(m) x 2(n), warp tile 32x64; CTA tile 128x128; k-chunk = 64
#define SKW 72   // smem row stride in halves

__device__ __forceinline__ void mma16816(float* c, const uint32_t* a, const uint32_t* b) {
    asm volatile("mma.sync.aligned.m16n8k16.row.col.f32.bf16.bf16.f32 "
        "{%0,%1,%2,%3}, {%4,%5,%6,%7}, {%8,%9}, {%0,%1,%2,%3};"
        : "+f"(c[0]), "+f"(c[1]), "+f"(c[2]), "+f"(c[3])
        : "r"(a[0]), "r"(a[1]), "r"(a[2]), "r"(a[3]), "r"(b[0]), "r"(b[1]));
}

__device__ __forceinline__ void load_chunk(const __nv_bfloat16* __restrict__ src,
                                           int ld, int row0, int k0,
                                           __nv_bfloat16 (*S)[SKW], int tid) {
    #pragma unroll
    for (int i = 0; i < 4; i++) {
        int c = tid + i * 256;
        int row = c >> 3;
        int kk = (c & 7) * 8;
        float4 v = *(const float4*)(src + (size_t)(row0 + row) * ld + k0 + kk);
        *(float4*)&S[row][kk] = v;
    }
}

__device__ __forceinline__ void mma_chunk(const __nv_bfloat16 (*As)[SKW],
                                          const __nv_bfloat16 (*Bs)[SKW],
                                          float c[2][8][4],
                                          int warp_m, int warp_n, int lane) {
    int g = lane >> 2, tig = lane & 3;
    #pragma unroll
    for (int ks = 0; ks < 4; ks++) {
        int k0 = ks * 16;
        uint32_t a[2][4], b[8][2];
        #pragma unroll
        for (int mt = 0; mt < 2; mt++) {
            int r = warp_m * 32 + mt * 16 + g;
            a[mt][0] = *(const uint32_t*)&As[r][k0 + tig * 2];
            a[mt][1] = *(const uint32_t*)&As[r + 8][k0 + tig * 2];
            a[mt][2] = *(const uint32_t*)&As[r][k0 + tig * 2 + 8];
            a[mt][3] = *(const uint32_t*)&As[r + 8][k0 + tig * 2 + 8];
        }
        #pragma unroll
        for (int nt = 0; nt < 8; nt++) {
            int n = warp_n * 64 + nt * 8 + g;
            b[nt][0] = *(const uint32_t*)&Bs[n][k0 + tig * 2];
            b[nt][1] = *(const uint32_t*)&Bs[n][k0 + tig * 2 + 8];
        }
        #pragma unroll
        for (int mt = 0; mt < 2; mt++)
            #pragma unroll
            for (int nt = 0; nt < 8; nt++)
                mma16816(c[mt][nt], a[mt], b[nt]);
    }
}

// ===================== GEMM1: h1 = x @ W1  (+ fused al1) ====================
__global__ __launch_bounds__(256) void gemm1_kernel(const float* __restrict__ as1,
                                                    const float* __restrict__ ad1) {
    __shared__ __nv_bfloat16 As[128][SKW];
    __shared__ __nv_bfloat16 Bs[128][SKW];
    __shared__ float sAls[128], sAld[128], s_as[128], s_ad[128];

    int tid = threadIdx.x;
    int wid = tid >> 5, lane = tid & 31;
    int warp_m = wid & 3, warp_n = wid >> 2;
    int g = lane >> 2, tig = lane & 3;
    int h = blockIdx.x;
    int m0 = blockIdx.y * MT;

    if (tid < 128) {
        sAls[tid] = 0.f; sAld[tid] = 0.f;
        s_as[tid] = as1[h * EMBED + tid];
        s_ad[tid] = ad1[h * EMBED + tid];
    }

    float c[2][8][4];
    #pragma unroll
    for (int mt = 0; mt < 2; mt++)
        #pragma unroll
        for (int nt = 0; nt < 8; nt++)
            #pragma unroll
            for (int i = 0; i < 4; i++) c[mt][nt][i] = 0.f;

    #pragma unroll
    for (int it = 0; it < 6; it++) {
        int p = it >> 1, kc = it & 1;
        const __nv_bfloat16* Asrc = (p == 2) ? g_xlo : g_xhi;
        const __nv_bfloat16* Bsrc = (p == 1) ? g_w1t_lo : g_w1t_hi;
        load_chunk(Asrc, EMBED, m0, kc * 64, As, tid);
        load_chunk(Bsrc, EMBED, h * 128, kc * 64, Bs, tid);
        __syncthreads();
        mma_chunk(As, Bs, c, warp_m, warp_n, lane);
        __syncthreads();
    }

    // epilogue: store h1 tile + attention logit partials
    float ps[2][2] = {{0.f, 0.f}, {0.f, 0.f}};
    float pd[2][2] = {{0.f, 0.f}, {0.f, 0.f}};
    #pragma unroll
    for (int mt = 0; mt < 2; mt++) {
        int r = warp_m * 32 + mt * 16 + g;
        #pragma unroll
        for (int nt = 0; nt < 8; nt++) {
            int col = warp_n * 64 + nt * 8 + tig * 2;
            float* cc = c[mt][nt];
            float a0 = s_as[col], a1 = s_as[col + 1];
            float d0 = s_ad[col], d1 = s_ad[col + 1];
            ps[mt][0] += cc[0] * a0 + cc[1] * a1;
            pd[mt][0] += cc[0] * d0 + cc[1] * d1;
            ps[mt][1] += cc[2] * a0 + cc[3] * a1;
            pd[mt][1] += cc[2] * d0 + cc[3] * d1;
            size_t base = (size_t)(m0 + r) * HC + h * EMBED + col;
            *(float2*)(g_h1 + base) = make_float2(cc[0], cc[1]);
            *(float2*)(g_h1 + base + 8 * HC) = make_float2(cc[2], cc[3]);
        }
    }
    #pragma unroll
    for (int o = 1; o <= 2; o <<= 1) {
        #pragma unroll
        for (int mt = 0; mt < 2; mt++)
            #pragma unroll
            for (int q = 0; q < 2; q++) {
                ps[mt][q] += __shfl_xor_sync(0xffffffffu, ps[mt][q], o);
                pd[mt][q] += __shfl_xor_sync(0xffffffffu, pd[mt][q], o);
            }
    }
    if (tig == 0) {
        #pragma unroll
        for (int mt = 0; mt < 2; mt++) {
            int r = warp_m * 32 + mt * 16 + g;
            atomicAdd(&sAls[r], ps[mt][0]);
            atomicAdd(&sAld[r], pd[mt][0]);
            atomicAdd(&sAls[r + 8], ps[mt][1]);
            atomicAdd(&sAld[r + 8], pd[mt][1]);
        }
    }
    __syncthreads();
    if (tid < 128) {
        g_als1[(m0 + tid) * HEADS + h] = sAls[tid];
        g_ald1[(m0 + tid) * HEADS + h] = sAld[tid];
    }
}

// ===================== agg1 =================================================
__global__ void agg1_kernel(const float* __restrict__ b1) {
    int nno = blockIdx.x;
    int t = threadIdx.x;
    int h = t >> 4;
    int c0 = (t & 15) * 8;
    int beg = g_rowptr[nno], end = g_rowptr[nno + 1];
    float ad = g_ald1[nno * HEADS + h];
    float m = M_SENT, s = 0.f;
    float a[8];
    #pragma unroll
    for (int i = 0; i < 8; i++) a[i] = 0.f;

    for (int j = beg; j < end; j++) {
        int src = __ldg(&g_col[j]);
        float lg = __ldg(&g_als1[src * HEADS + h]) + ad;
        lg = lg > 0.f ? lg : NEG_SLOPE * lg;
        const float4* hp = (const float4*)(g_h1 + (size_t)src * HC + h * EMBED + c0);
        float4 h0 = __ldg(hp), h1v = __ldg(hp + 1);
        float hv[8] = {h0.x, h0.y, h0.z, h0.w, h1v.x, h1v.y, h1v.z, h1v.w};
        if (lg > m) {
            float sc = (m == M_SENT) ? 0.f : __expf(m - lg);
            s = s * sc + 1.f;
            #pragma unroll
            for (int i = 0; i < 8; i++) a[i] = a[i] * sc + hv[i];
            m = lg;
        } else {
            float p = __expf(lg - m);
            s += p;
            #pragma unroll
            for (int i = 0; i < 8; i++) a[i] += p * hv[i];
        }
    }
    float inv = 1.f / (s + 1e-16f);
    __align__(16) __nv_bfloat16 hb[8], lb[8];
    #pragma unroll
    for (int i = 0; i < 8; i++) {
        float v = a[i] * inv + b1[h * EMBED + c0 + i];
        v = v > 0.f ? v : (__expf(v) - 1.f);
        __nv_bfloat16 hi = __float2bfloat16(v);
        hb[i] = hi;
        lb[i] = __float2bfloat16(v - __bfloat162float(hi));
    }
    size_t off = (size_t)nno * HC + h * EMBED + c0;
    *(float4*)(g_x2hi + off) = *(float4*)hb;
    *(float4*)(g_x2lo + off) = *(float4*)lb;
}

// ===================== GEMM2: h2 = x2 @ W2  (+ fused al2) ===================
__global__ __launch_bounds__(256) void gemm2_kernel(const float* __restrict__ as2,
                                                    const float* __restrict__ ad2) {
    __shared__ __nv_bfloat16 As[128][SKW];
    __shared__ __nv_bfloat16 Bs[128][SKW];
    __shared__ float sAls[128], sAld[128], s_as[128], s_ad[128];

    int tid = threadIdx.x;
    int wid = tid >> 5, lane = tid & 31;
    int warp_m = wid & 3, warp_n = wid >> 2;
    int g = lane >> 2, tig = lane & 3;
    int m0 = blockIdx.x * MT;

    if (tid < 128) {
        sAls[tid] = 0.f; sAld[tid] = 0.f;
        s_as[tid] = as2[tid];
        s_ad[tid] = ad2[tid];
    }

    float c[2][8][4];
    #pragma unroll
    for (int mt = 0; mt < 2; mt++)
        #pragma unroll
        for (int nt = 0; nt < 8; nt++)
            #pragma unroll
            for (int i = 0; i < 4; i++) c[mt][nt][i] = 0.f;

    for (int it = 0; it < 96; it++) {
        int p = it >> 5, kc = it & 31;
        const __nv_bfloat16* Asrc = (p == 2) ? g_x2lo : g_x2hi;
        const __nv_bfloat16* Bsrc = (p == 1) ? g_w2t_lo : g_w2t_hi;
        load_chunk(Asrc, HC, m0, kc * 64, As, tid);
        load_chunk(Bsrc, HC, 0, kc * 64, Bs, tid);
        __syncthreads();
        mma_chunk(As, Bs, c, warp_m, warp_n, lane);
        __syncthreads();
    }

    float ps[2][2] = {{0.f, 0.f}, {0.f, 0.f}};
    float pd[2][2] = {{0.f, 0.f}, {0.f, 0.f}};
    #pragma unroll
    for (int mt = 0; mt < 2; mt++) {
        int r = warp_m * 32 + mt * 16 + g;
        #pragma unroll
        for (int nt = 0; nt < 8; nt++) {
            int col = warp_n * 64 + nt * 8 + tig * 2;
            float* cc = c[mt][nt];
            float a0 = s_as[col], a1 = s_as[col + 1];
            float d0 = s_ad[col], d1 = s_ad[col + 1];
            ps[mt][0] += cc[0] * a0 + cc[1] * a1;
            pd[mt][0] += cc[0] * d0 + cc[1] * d1;
            ps[mt][1] += cc[2] * a0 + cc[3] * a1;
            pd[mt][1] += cc[2] * d0 + cc[3] * d1;
            size_t base = (size_t)(m0 + r) * EMBED + col;
            *(float2*)(g_h2 + base) = make_float2(cc[0], cc[1]);
            *(float2*)(g_h2 + base + 8 * EMBED) = make_float2(cc[2], cc[3]);
        }
    }
    #pragma unroll
    for (int o = 1; o <= 2; o <<= 1) {
        #pragma unroll
        for (int mt = 0; mt < 2; mt++)
            #pragma unroll
            for (int q = 0; q < 2; q++) {
                ps[mt][q] += __shfl_xor_sync(0xffffffffu, ps[mt][q], o);
                pd[mt][q] += __shfl_xor_sync(0xffffffffu, pd[mt][q], o);
            }
    }
    if (tig == 0) {
        #pragma unroll
        for (int mt = 0; mt < 2; mt++) {
            int r = warp_m * 32 + mt * 16 + g;
            atomicAdd(&sAls[r], ps[mt][0]);
            atomicAdd(&sAld[r], pd[mt][0]);
            atomicAdd(&sAls[r + 8], ps[mt][1]);
            atomicAdd(&sAld[r + 8], pd[mt][1]);
        }
    }
    __syncthreads();
    if (tid < 128) {
        g_als2[m0 + tid] = sAls[tid];
        g_ald2[m0 + tid] = sAld[tid];
    }
}

// ===================== agg2 + classifier fused ==============================
__global__ void agg2cls_kernel(const float* __restrict__ b2,
                               const float* __restrict__ Wc,
                               const float* __restrict__ bc,
                               float* __restrict__ out) {
    int nno = blockIdx.x;
    int c = threadIdx.x;
    int beg = g_rowptr[nno], end = g_rowptr[nno + 1];
    float ad = g_ald2[nno];
    float m = M_SENT, s = 0.f, acc = 0.f;
    for (int j = beg; j < end; j++) {
        int src = __ldg(&g_col[j]);
        float lg = __ldg(&g_als2[src]) + ad;
        lg = lg > 0.f ? lg : NEG_SLOPE * lg;
        float hv = __ldg(&g_h2[(size_t)src * EMBED + c]);
        if (lg > m) {
            float sc = (m == M_SENT) ? 0.f : __expf(m - lg);
            s = s * sc + 1.f;
            acc = acc * sc + hv;
            m = lg;
        } else {
            float p = __expf(lg - m);
            s += p;
            acc += p * hv;
        }
    }
    float val = acc / (s + 1e-16f) + b2[c];
    float part = val * __ldg(&Wc[c]);
    #pragma unroll
    for (int o = 16; o > 0; o >>= 1) part += __shfl_down_sync(0xffffffffu, part, o);
    __shared__ float ws[4];
    if ((c & 31) == 0) ws[c >> 5] = part;
    __syncthreads();
    if (c == 0) out[nno] = ws[0] + ws[1] + ws[2] + ws[3] + bc[0];
}

// ===================== launch ===============================================
extern "C" void kernel_launch(void* const* d_in, const int* in_sizes, int n_in,
                              void* d_out, int out_size) {
    const float* x   = (const float*)d_in[0];
    const void*  ei  = d_in[1];
    const float* W1  = (const float*)d_in[2];
    const float* as1 = (const float*)d_in[3];
    const float* ad1 = (const float*)d_in[4];
    const float* b1  = (const float*)d_in[5];
    const float* W2  = (const float*)d_in[6];
    const float* as2 = (const float*)d_in[7];
    const float* ad2 = (const float*)d_in[8];
    const float* b2  = (const float*)d_in[9];
    const float* Wc  = (const float*)d_in[10];
    const float* bc  = (const float*)d_in[11];
    float* out = (float*)d_out;

    int E = in_sizes[1] / 2;
    int n = in_sizes[0] / EMBED;
    int mtiles = (n + MT - 1) / MT;

    prep_kernel<<<NB_X + NB_W1 + NB_W2 + NB_DEG + 1, 256>>>(x, W1, W2, ei);   // 0
    decode_count_kernel<<<(2 * E + 255) / 256, 256>>>(ei, E);                 // 1
    scan_kernel<<<1, 1024>>>(n);                                              // 2
    fill_kernel<<<(E + n + 255) / 256, 256>>>(E, n);                          // 3
    gemm1_kernel<<<dim3(HEADS, mtiles), 256>>>(as1, ad1);                     // 4
    agg1_kernel<<<n, 256>>>(b1);                                              // 5 <- profiled
    gemm2_kernel<<<mtiles, 256>>>(as2, ad2);                                  // 6
    agg2cls_kernel<<<n, 128>>>(b2, Wc, bc, out);                              // 7
}

// round 6
// speedup vs baseline: 1.5662x; 1.2786x over previous
#include <cuda_runtime.h>
#include <cuda_bf16.h>
#include <cuda_fp16.h>
#include <cstdint>

#define N_NODES 10000
#define EDGES   160000
#define EMBED   128
#define HEADS   16
#define HC      2048
#define NEG_SLOPE 0.2f
#define M_SENT  (-1e30f)
#define MT      128
#define MTILES  79
#define MPAD    (MTILES * MT)      // 10112
#define KSPLIT  4

// ===================== device scratch =======================================
__device__ int   g_is64;
__device__ int   g_src[EDGES];
__device__ int   g_dst[EDGES];
__device__ int   g_deg[N_NODES];
__device__ int   g_rowptr[N_NODES + 1];
__device__ int   g_cursor[N_NODES];
__device__ int   g_col[EDGES + N_NODES];

__device__ __nv_bfloat16 g_xhi[(size_t)MPAD * EMBED];
__device__ __nv_bfloat16 g_xlo[(size_t)MPAD * EMBED];
__device__ __nv_bfloat16 g_w1t_hi[(size_t)HC * EMBED];   // [n=2048][k=128]
__device__ __nv_bfloat16 g_w1t_lo[(size_t)HC * EMBED];
__device__ __nv_bfloat16 g_w2t_hi[(size_t)EMBED * HC];   // [n=128][k=2048]
__device__ __nv_bfloat16 g_w2t_lo[(size_t)EMBED * HC];
__device__ __half g_h1[(size_t)MPAD * HC];               // 41.4 MB fp16
__device__ float g_als1[MPAD * HEADS];
__device__ float g_ald1[MPAD * HEADS];
__device__ __nv_bfloat16 g_x2hi[(size_t)MPAD * HC];
__device__ __nv_bfloat16 g_x2lo[(size_t)MPAD * HC];
__device__ float g_h2p[(size_t)KSPLIT * MPAD * EMBED];   // 20.7 MB partials
__device__ __half g_h2[(size_t)MPAD * EMBED];            // fp16
__device__ float g_als2[MPAD];
__device__ float g_ald2[MPAD];

// ===================== prep =================================================
template <int R, int C>
__device__ void transpose_cv(const float* __restrict__ src,
                             __nv_bfloat16* __restrict__ dhi,
                             __nv_bfloat16* __restrict__ dlo, int bx, int by) {
    __shared__ float tile[32][33];
    int tx = threadIdx.x & 31, ty0 = threadIdx.x >> 5;
    #pragma unroll
    for (int j = 0; j < 4; j++) {
        int r = by * 32 + ty0 + j * 8, c = bx * 32 + tx;
        tile[ty0 + j * 8][tx] = src[(size_t)r * C + c];
    }
    __syncthreads();
    #pragma unroll
    for (int j = 0; j < 4; j++) {
        int rd = bx * 32 + ty0 + j * 8;
        int cd = by * 32 + tx;
        float v = tile[tx][ty0 + j * 8];
        __nv_bfloat16 h = __float2bfloat16(v);
        dhi[(size_t)rd * R + cd] = h;
        dlo[(size_t)rd * R + cd] = __float2bfloat16(v - __bfloat162float(h));
    }
}

#define NB_X   5000
#define NB_W1  256
#define NB_W2  256
#define NB_DEG 40

__global__ void prep_kernel(const float* __restrict__ x,
                            const float* __restrict__ W1,
                            const float* __restrict__ W2,
                            const void* __restrict__ ei) {
    int b = blockIdx.x, t = threadIdx.x;
    if (b < NB_X) {
        int idx = b * 256 + t;
        if (idx < N_NODES * EMBED) {
            float v = x[idx];
            __nv_bfloat16 h = __float2bfloat16(v);
            g_xhi[idx] = h;
            g_xlo[idx] = __float2bfloat16(v - __bfloat162float(h));
        }
        return;
    }
    b -= NB_X;
    if (b < NB_W1) { transpose_cv<128, 2048>(W1, g_w1t_hi, g_w1t_lo, b & 63, b >> 6); return; }
    b -= NB_W1;
    if (b < NB_W2) { transpose_cv<2048, 128>(W2, g_w2t_hi, g_w2t_lo, b & 3, b >> 2); return; }
    b -= NB_W2;
    if (b < NB_DEG) {
        int idx = b * 256 + t;
        if (idx < N_NODES) g_deg[idx] = 1;
        return;
    }
    const long long* p = (const long long*)ei;
    long long v = p[t];
    int ok = (v >= 0 && v < N_NODES);
    int all = __syncthreads_and(ok);
    if (t == 0) g_is64 = all;
}

__global__ void decode_count_kernel(const void* __restrict__ ei, int E) {
    int i = blockIdx.x * blockDim.x + threadIdx.x;
    if (i >= 2 * E) return;
    int vi = g_is64 ? (int)((const long long*)ei)[i] : ((const int*)ei)[i];
    if (i < E) g_src[i] = vi;
    else { g_dst[i - E] = vi; atomicAdd(&g_deg[vi], 1); }
}

__global__ void scan_kernel(int n) {
    __shared__ int wsum[32];
    int tid = threadIdx.x;
    int CH = (n + 1023) / 1024;
    int base = tid * CH;
    int s = 0;
    for (int k = 0; k < CH; k++) { int idx = base + k; if (idx < n) s += g_deg[idx]; }
    int lane = tid & 31, wid = tid >> 5;
    int v = s;
    #pragma unroll
    for (int o = 1; o < 32; o <<= 1) {
        int t2 = __shfl_up_sync(0xffffffffu, v, o);
        if (lane >= o) v += t2;
    }
    if (lane == 31) wsum[wid] = v;
    __syncthreads();
    if (wid == 0) {
        int w = wsum[lane];
        #pragma unroll
        for (int o = 1; o < 32; o <<= 1) {
            int t2 = __shfl_up_sync(0xffffffffu, w, o);
            if (lane >= o) w += t2;
        }
        wsum[lane] = w;
    }
    __syncthreads();
    int excl = v - s + (wid ? wsum[wid - 1] : 0);
    int running = excl;
    for (int k = 0; k < CH; k++) {
        int idx = base + k;
        if (idx < n) {
            g_rowptr[idx] = running;
            g_cursor[idx] = running;
            running += g_deg[idx];
        }
    }
    if (tid == 0) g_rowptr[n] = wsum[31];
}

__global__ void fill_kernel(int E, int n) {
    int i = blockIdx.x * blockDim.x + threadIdx.x;
    if (i < E) {
        int d = g_dst[i];
        int pos = atomicAdd(&g_cursor[d], 1);
        g_col[pos] = g_src[i];
    } else if (i < E + n) {
        int v = i - E;
        int pos = atomicAdd(&g_cursor[v], 1);
        g_col[pos] = v;
    }
}

// ===================== mma.sync GEMM machinery ==============================
#define SKW 72
#define CHUNK_B (128 * SKW * 2)   // 18432 bytes per 128x64 chunk

__device__ __forceinline__ void mma16816(float* c, const uint32_t* a, const uint32_t* b) {
    asm volatile("mma.sync.aligned.m16n8k16.row.col.f32.bf16.bf16.f32 "
        "{%0,%1,%2,%3}, {%4,%5,%6,%7}, {%8,%9}, {%0,%1,%2,%3};"
        : "+f"(c[0]), "+f"(c[1]), "+f"(c[2]), "+f"(c[3])
        : "r"(a[0]), "r"(a[1]), "r"(a[2]), "r"(a[3]), "r"(b[0]), "r"(b[1]));
}

__device__ __forceinline__ void fetch_chunk(const __nv_bfloat16* __restrict__ src,
                                            int ld, int row0, int k0,
                                            float4* r, int tid) {
    #pragma unroll
    for (int i = 0; i < 4; i++) {
        int c = tid + i * 256;
        int row = c >> 3;
        int kk = (c & 7) * 8;
        r[i] = *(const float4*)(src + (size_t)(row0 + row) * ld + k0 + kk);
    }
}

__device__ __forceinline__ void stash_chunk(const float4* r,
                                            __nv_bfloat16 (*S)[SKW], int tid) {
    #pragma unroll
    for (int i = 0; i < 4; i++) {
        int c = tid + i * 256;
        int row = c >> 3;
        int kk = (c & 7) * 8;
        *(float4*)&S[row][kk] = r[i];
    }
}

__device__ __forceinline__ void mma_chunk(const __nv_bfloat16 (*As)[SKW],
                                          const __nv_bfloat16 (*Bs)[SKW],
                                          float c[2][8][4],
                                          int warp_m, int warp_n, int lane) {
    int g = lane >> 2, tig = lane & 3;
    #pragma unroll
    for (int ks = 0; ks < 4; ks++) {
        int k0 = ks * 16;
        uint32_t a[2][4], b[8][2];
        #pragma unroll
        for (int mt = 0; mt < 2; mt++) {
            int r = warp_m * 32 + mt * 16 + g;
            a[mt][0] = *(const uint32_t*)&As[r][k0 + tig * 2];
            a[mt][1] = *(const uint32_t*)&As[r + 8][k0 + tig * 2];
            a[mt][2] = *(const uint32_t*)&As[r][k0 + tig * 2 + 8];
            a[mt][3] = *(const uint32_t*)&As[r + 8][k0 + tig * 2 + 8];
        }
        #pragma unroll
        for (int nt = 0; nt < 8; nt++) {
            int n = warp_n * 64 + nt * 8 + g;
            b[nt][0] = *(const uint32_t*)&Bs[n][k0 + tig * 2];
            b[nt][1] = *(const uint32_t*)&Bs[n][k0 + tig * 2 + 8];
        }
        #pragma unroll
        for (int mt = 0; mt < 2; mt++)
            #pragma unroll
            for (int nt = 0; nt < 8; nt++)
                mma16816(c[mt][nt], a[mt], b[nt]);
    }
}

// ===================== GEMM1: h1 = x @ W1  (+ fused al1), fp16 out ==========
#define G1_SMEM (4 * CHUNK_B + 4 * 128 * 4)

__global__ __launch_bounds__(256) void gemm1_kernel(const float* __restrict__ as1,
                                                    const float* __restrict__ ad1) {
    extern __shared__ char dsm[];
    __nv_bfloat16 (*Ab[2])[SKW] = {(__nv_bfloat16(*)[SKW])dsm,
                                   (__nv_bfloat16(*)[SKW])(dsm + 2 * CHUNK_B)};
    __nv_bfloat16 (*Bb[2])[SKW] = {(__nv_bfloat16(*)[SKW])(dsm + CHUNK_B),
                                   (__nv_bfloat16(*)[SKW])(dsm + 3 * CHUNK_B)};
    float* sAls = (float*)(dsm + 4 * CHUNK_B);
    float* sAld = sAls + 128;
    float* s_as = sAld + 128;
    float* s_ad = s_as + 128;

    int tid = threadIdx.x;
    int wid = tid >> 5, lane = tid & 31;
    int warp_m = wid & 3, warp_n = wid >> 2;
    int g = lane >> 2, tig = lane & 3;
    int h = blockIdx.x;
    int m0 = blockIdx.y * MT;

    if (tid < 128) {
        sAls[tid] = 0.f; sAld[tid] = 0.f;
        s_as[tid] = as1[h * EMBED + tid];
        s_ad[tid] = ad1[h * EMBED + tid];
    }

    float c[2][8][4];
    #pragma unroll
    for (int mt = 0; mt < 2; mt++)
        #pragma unroll
        for (int nt = 0; nt < 8; nt++)
            #pragma unroll
            for (int i = 0; i < 4; i++) c[mt][nt][i] = 0.f;

    // chunk schedule: hi/hi k0,k1; hi/lo k0,k1; lo/hi k0,k1
    float4 pa[4], pb[4];
    fetch_chunk(g_xhi, EMBED, m0, 0, pa, tid);
    fetch_chunk(g_w1t_hi, EMBED, h * 128, 0, pb, tid);
    #pragma unroll
    for (int it = 0; it < 6; it++) {
        stash_chunk(pa, Ab[it & 1], tid);
        stash_chunk(pb, Bb[it & 1], tid);
        __syncthreads();
        if (it + 1 < 6) {
            int nx = it + 1;
            int p = nx >> 1, kc = (nx & 1) * 64;
            const __nv_bfloat16* Asrc = (p == 2) ? g_xlo : g_xhi;
            const __nv_bfloat16* Bsrc = (p == 1) ? g_w1t_lo : g_w1t_hi;
            fetch_chunk(Asrc, EMBED, m0, kc, pa, tid);
            fetch_chunk(Bsrc, EMBED, h * 128, kc, pb, tid);
        }
        mma_chunk(Ab[it & 1], Bb[it & 1], c, warp_m, warp_n, lane);
        __syncthreads();
    }

    // epilogue: fp16 h1 store + fused attention logits
    float ps[2][2] = {{0.f, 0.f}, {0.f, 0.f}};
    float pd[2][2] = {{0.f, 0.f}, {0.f, 0.f}};
    #pragma unroll
    for (int mt = 0; mt < 2; mt++) {
        int r = warp_m * 32 + mt * 16 + g;
        #pragma unroll
        for (int nt = 0; nt < 8; nt++) {
            int col = warp_n * 64 + nt * 8 + tig * 2;
            float* cc = c[mt][nt];
            float a0 = s_as[col], a1 = s_as[col + 1];
            float d0 = s_ad[col], d1 = s_ad[col + 1];
            ps[mt][0] += cc[0] * a0 + cc[1] * a1;
            pd[mt][0] += cc[0] * d0 + cc[1] * d1;
            ps[mt][1] += cc[2] * a0 + cc[3] * a1;
            pd[mt][1] += cc[2] * d0 + cc[3] * d1;
            size_t base = (size_t)(m0 + r) * HC + h * EMBED + col;
            *(__half2*)(g_h1 + base) = __floats2half2_rn(cc[0], cc[1]);
            *(__half2*)(g_h1 + base + 8 * HC) = __floats2half2_rn(cc[2], cc[3]);
        }
    }
    #pragma unroll
    for (int o = 1; o <= 2; o <<= 1) {
        #pragma unroll
        for (int mt = 0; mt < 2; mt++)
            #pragma unroll
            for (int q = 0; q < 2; q++) {
                ps[mt][q] += __shfl_xor_sync(0xffffffffu, ps[mt][q], o);
                pd[mt][q] += __shfl_xor_sync(0xffffffffu, pd[mt][q], o);
            }
    }
    if (tig == 0) {
        #pragma unroll
        for (int mt = 0; mt < 2; mt++) {
            int r = warp_m * 32 + mt * 16 + g;
            atomicAdd(&sAls[r], ps[mt][0]);
            atomicAdd(&sAld[r], pd[mt][0]);
            atomicAdd(&sAls[r + 8], ps[mt][1]);
            atomicAdd(&sAld[r + 8], pd[mt][1]);
        }
    }
    __syncthreads();
    if (tid < 128) {
        g_als1[(m0 + tid) * HEADS + h] = sAls[tid];
        g_ald1[(m0 + tid) * HEADS + h] = sAld[tid];
    }
}

// ===================== agg1 (fp16 gather) ===================================
__global__ void agg1_kernel(const float* __restrict__ b1) {
    int nno = blockIdx.x;
    int t = threadIdx.x;
    int h = t >> 4;
    int c0 = (t & 15) * 8;
    int beg = g_rowptr[nno], end = g_rowptr[nno + 1];
    float ad = g_ald1[nno * HEADS + h];
    float m = M_SENT, s = 0.f;
    float a[8];
    #pragma unroll
    for (int i = 0; i < 8; i++) a[i] = 0.f;

    for (int j = beg; j < end; j++) {
        int src = __ldg(&g_col[j]);
        float lg = __ldg(&g_als1[src * HEADS + h]) + ad;
        lg = lg > 0.f ? lg : NEG_SLOPE * lg;
        uint4 u = __ldg((const uint4*)(g_h1 + (size_t)src * HC + h * EMBED + c0));
        const __half2* hh = (const __half2*)&u;
        float2 f0 = __half22float2(hh[0]), f1 = __half22float2(hh[1]);
        float2 f2 = __half22float2(hh[2]), f3 = __half22float2(hh[3]);
        float hv[8] = {f0.x, f0.y, f1.x, f1.y, f2.x, f2.y, f3.x, f3.y};
        if (lg > m) {
            float sc = (m == M_SENT) ? 0.f : __expf(m - lg);
            s = s * sc + 1.f;
            #pragma unroll
            for (int i = 0; i < 8; i++) a[i] = a[i] * sc + hv[i];
            m = lg;
        } else {
            float p = __expf(lg - m);
            s += p;
            #pragma unroll
            for (int i = 0; i < 8; i++) a[i] += p * hv[i];
        }
    }
    float inv = 1.f / (s + 1e-16f);
    __align__(16) __nv_bfloat16 hb[8], lb[8];
    #pragma unroll
    for (int i = 0; i < 8; i++) {
        float v = a[i] * inv + b1[h * EMBED + c0 + i];
        v = v > 0.f ? v : (__expf(v) - 1.f);
        __nv_bfloat16 hi = __float2bfloat16(v);
        hb[i] = hi;
        lb[i] = __float2bfloat16(v - __bfloat162float(hi));
    }
    size_t off = (size_t)nno * HC + h * EMBED + c0;
    *(float4*)(g_x2hi + off) = *(float4*)hb;
    *(float4*)(g_x2lo + off) = *(float4*)lb;
}

// ===================== GEMM2: K-split partials ==============================
#define G2_SMEM (4 * CHUNK_B)
#define G2_NIT  24   // 3 passes x 8 k-chunks (512 per split)

__global__ __launch_bounds__(256) void gemm2_kernel() {
    extern __shared__ char dsm[];
    __nv_bfloat16 (*Ab[2])[SKW] = {(__nv_bfloat16(*)[SKW])dsm,
                                   (__nv_bfloat16(*)[SKW])(dsm + 2 * CHUNK_B)};
    __nv_bfloat16 (*Bb[2])[SKW] = {(__nv_bfloat16(*)[SKW])(dsm + CHUNK_B),
                                   (__nv_bfloat16(*)[SKW])(dsm + 3 * CHUNK_B)};

    int tid = threadIdx.x;
    int wid = tid >> 5, lane = tid & 31;
    int warp_m = wid & 3, warp_n = wid >> 2;
    int g = lane >> 2, tig = lane & 3;
    int m0 = blockIdx.x * MT;
    int ks = blockIdx.y * 512;          // K-split base

    float c[2][8][4];
    #pragma unroll
    for (int mt = 0; mt < 2; mt++)
        #pragma unroll
        for (int nt = 0; nt < 8; nt++)
            #pragma unroll
            for (int i = 0; i < 4; i++) c[mt][nt][i] = 0.f;

    float4 pa[4], pb[4];
    fetch_chunk(g_x2hi, HC, m0, ks, pa, tid);
    fetch_chunk(g_w2t_hi, HC, 0, ks, pb, tid);
    for (int it = 0; it < G2_NIT; it++) {
        stash_chunk(pa, Ab[it & 1], tid);
        stash_chunk(pb, Bb[it & 1], tid);
        __syncthreads();
        if (it + 1 < G2_NIT) {
            int nx = it + 1;
            int p = nx >> 3, kc = ks + (nx & 7) * 64;
            const __nv_bfloat16* Asrc = (p == 2) ? g_x2lo : g_x2hi;
            const __nv_bfloat16* Bsrc = (p == 1) ? g_w2t_lo : g_w2t_hi;
            fetch_chunk(Asrc, HC, m0, kc, pa, tid);
            fetch_chunk(Bsrc, HC, 0, kc, pb, tid);
        }
        mma_chunk(Ab[it & 1], Bb[it & 1], c, warp_m, warp_n, lane);
        __syncthreads();
    }

    float* outp = g_h2p + (size_t)blockIdx.y * MPAD * EMBED;
    #pragma unroll
    for (int mt = 0; mt < 2; mt++) {
        int r = warp_m * 32 + mt * 16 + g;
        #pragma unroll
        for (int nt = 0; nt < 8; nt++) {
            int col = warp_n * 64 + nt * 8 + tig * 2;
            float* cc = c[mt][nt];
            size_t base = (size_t)(m0 + r) * EMBED + col;
            *(float2*)(outp + base) = make_float2(cc[0], cc[1]);
            *(float2*)(outp + base + 8 * EMBED) = make_float2(cc[2], cc[3]);
        }
    }
}

// ===================== combine partials + al2 ===============================
__global__ void combine_kernel(const float* __restrict__ as2,
                               const float* __restrict__ ad2, int n) {
    int t = threadIdx.x;
    int row = blockIdx.x * 2 + (t >> 7);
    int col = t & 127;
    if (row >= n) return;
    size_t idx = (size_t)row * EMBED + col;
    float s = g_h2p[idx] + g_h2p[idx + (size_t)MPAD * EMBED]
            + g_h2p[idx + 2 * (size_t)MPAD * EMBED]
            + g_h2p[idx + 3 * (size_t)MPAD * EMBED];
    g_h2[idx] = __float2half(s);
    float a = s * __ldg(&as2[col]);
    float d = s * __ldg(&ad2[col]);
    #pragma unroll
    for (int o = 16; o > 0; o >>= 1) {
        a += __shfl_down_sync(0xffffffffu, a, o);
        d += __shfl_down_sync(0xffffffffu, d, o);
    }
    __shared__ float wa[8], wd[8];
    int w = t >> 5;
    if ((t & 31) == 0) { wa[w] = a; wd[w] = d; }
    __syncthreads();
    if ((t & 127) == 0) {
        int wb = (t >> 7) * 4;
        g_als2[row] = wa[wb] + wa[wb + 1] + wa[wb + 2] + wa[wb + 3];
        g_ald2[row] = wd[wb] + wd[wb + 1] + wd[wb + 2] + wd[wb + 3];
    }
}

// ===================== agg2 + classifier fused ==============================
__global__ void agg2cls_kernel(const float* __restrict__ b2,
                               const float* __restrict__ Wc,
                               const float* __restrict__ bc,
                               float* __restrict__ out) {
    int nno = blockIdx.x;
    int c = threadIdx.x;
    int beg = g_rowptr[nno], end = g_rowptr[nno + 1];
    float ad = g_ald2[nno];
    float m = M_SENT, s = 0.f, acc = 0.f;
    for (int j = beg; j < end; j++) {
        int src = __ldg(&g_col[j]);
        float lg = __ldg(&g_als2[src]) + ad;
        lg = lg > 0.f ? lg : NEG_SLOPE * lg;
        float hv = __half2float(__ldg(&g_h2[(size_t)src * EMBED + c]));
        if (lg > m) {
            float sc = (m == M_SENT) ? 0.f : __expf(m - lg);
            s = s * sc + 1.f;
            acc = acc * sc + hv;
            m = lg;
        } else {
            float p = __expf(lg - m);
            s += p;
            acc += p * hv;
        }
    }
    float val = acc / (s + 1e-16f) + b2[c];
    float part = val * __ldg(&Wc[c]);
    #pragma unroll
    for (int o = 16; o > 0; o >>= 1) part += __shfl_down_sync(0xffffffffu, part, o);
    __shared__ float ws[4];
    if ((c & 31) == 0) ws[c >> 5] = part;
    __syncthreads();
    if (c == 0) out[nno] = ws[0] + ws[1] + ws[2] + ws[3] + bc[0];
}

// ===================== launch ===============================================
extern "C" void kernel_launch(void* const* d_in, const int* in_sizes, int n_in,
                              void* d_out, int out_size) {
    const float* x   = (const float*)d_in[0];
    const void*  ei  = d_in[1];
    const float* W1  = (const float*)d_in[2];
    const float* as1 = (const float*)d_in[3];
    const float* ad1 = (const float*)d_in[4];
    const float* b1  = (const float*)d_in[5];
    const float* W2  = (const float*)d_in[6];
    const float* as2 = (const float*)d_in[7];
    const float* ad2 = (const float*)d_in[8];
    const float* b2  = (const float*)d_in[9];
    const float* Wc  = (const float*)d_in[10];
    const float* bc  = (const float*)d_in[11];
    float* out = (float*)d_out;

    int E = in_sizes[1] / 2;
    int n = in_sizes[0] / EMBED;
    int mtiles = (n + MT - 1) / MT;

    cudaFuncSetAttribute(gemm1_kernel, cudaFuncAttributeMaxDynamicSharedMemorySize, G1_SMEM);
    cudaFuncSetAttribute(gemm2_kernel, cudaFuncAttributeMaxDynamicSharedMemorySize, G2_SMEM);

    prep_kernel<<<NB_X + NB_W1 + NB_W2 + NB_DEG + 1, 256>>>(x, W1, W2, ei);
    decode_count_kernel<<<(2 * E + 255) / 256, 256>>>(ei, E);
    scan_kernel<<<1, 1024>>>(n);
    fill_kernel<<<(E + n + 255) / 256, 256>>>(E, n);
    gemm1_kernel<<<dim3(HEADS, mtiles), 256, G1_SMEM>>>(as1, ad1);
    agg1_kernel<<<n, 256>>>(b1);
    gemm2_kernel<<<dim3(mtiles, KSPLIT), 256, G2_SMEM>>>();
    combine_kernel<<<(n + 1) / 2, 256>>>(as2, ad2, n);
    agg2cls_kernel<<<n, 128>>>(b2, Wc, bc, out);
}